// round 14
// baseline (speedup 1.0000x reference)
#include <cuda_runtime.h>
#include <cuda_bf16.h>
#include <cstdint>
#include <math.h>

#define SEQ 2048
#define IND 1024
#define HD 256
#define NTOK 8192
typedef __nv_bfloat16 bf16;

// ---------------- scratch (no allocs allowed) ----------------
__device__ __align__(16) bf16 g_xqh[NTOK*IND], g_xql[NTOK*IND];
__device__ __align__(16) bf16 g_xkh[NTOK*IND], g_xkl[NTOK*IND];
__device__ __align__(16) bf16 g_wqt_h[HD*IND], g_wqt_l[HD*IND];   // [256][1024] K-major
__device__ __align__(16) bf16 g_wkt_h[HD*IND], g_wkt_l[HD*IND];
__device__ __align__(16) bf16 g_wvt_h[HD*IND], g_wvt_l[HD*IND];
__device__ __align__(16) bf16 g_wot_h[IND*HD], g_wot_l[IND*HD];   // [1024][256] K-major
__device__ __align__(16) float2 g_trq[NTOK*32], g_trk[NTOK*32];   // rope cos/sin tables
__device__ __align__(16) bf16 g_qh[NTOK*HD], g_ql[NTOK*HD];       // roped+scaled [bh][s][64]
__device__ __align__(16) bf16 g_kh[NTOK*HD], g_kl[NTOK*HD];
__device__ __align__(16) bf16 g_vh[NTOK*HD], g_vl[NTOK*HD];       // [bh][s][64]
__device__ __align__(16) bf16 g_aoh[NTOK*HD], g_aol[NTOK*HD];     // [tok][256]

__constant__ double c_invf[16] = {
    1.0, 0.5623413251903491, 0.31622776601683794, 0.17782794100389228,
    0.1, 0.05623413251903491, 0.031622776601683791, 0.017782794100389228,
    0.01, 0.005623413251903491, 0.0031622776601683794, 0.0017782794100389228,
    0.001, 0.0005623413251903491, 0.00031622776601683794, 0.00017782794100389228};

// ---------------- helpers ----------------
__device__ __forceinline__ uint32_t smem_u32(const void* p) {
    uint32_t a;
    asm("{ .reg .u64 t; cvta.to.shared.u64 t, %1; cvt.u32.u64 %0, t; }" : "=r"(a) : "l"(p));
    return a;
}
__device__ __forceinline__ void ldsm4(uint32_t a, uint32_t* r) {
    asm volatile("ldmatrix.sync.aligned.m8n8.x4.shared.b16 {%0,%1,%2,%3}, [%4];"
        : "=r"(r[0]), "=r"(r[1]), "=r"(r[2]), "=r"(r[3]) : "r"(a));
}
__device__ __forceinline__ void ldsm4t(uint32_t a, uint32_t* r) {
    asm volatile("ldmatrix.sync.aligned.m8n8.x4.trans.shared.b16 {%0,%1,%2,%3}, [%4];"
        : "=r"(r[0]), "=r"(r[1]), "=r"(r[2]), "=r"(r[3]) : "r"(a));
}
__device__ __forceinline__ void mma16816(float* c, const uint32_t* a, const uint32_t* b) {
    asm volatile("mma.sync.aligned.m16n8k16.row.col.f32.bf16.bf16.f32 "
        "{%0,%1,%2,%3}, {%4,%5,%6,%7}, {%8,%9}, {%0,%1,%2,%3};"
        : "+f"(c[0]), "+f"(c[1]), "+f"(c[2]), "+f"(c[3])
        : "r"(a[0]), "r"(a[1]), "r"(a[2]), "r"(a[3]), "r"(b[0]), "r"(b[1]));
}
__device__ __forceinline__ void cpa(uint32_t s, const void* g) {
    asm volatile("cp.async.cg.shared.global [%0], [%1], 16;" :: "r"(s), "l"(g));
}
__device__ __forceinline__ void cpc()  { asm volatile("cp.async.commit_group;" ::: "memory"); }
__device__ __forceinline__ void cpw1() { asm volatile("cp.async.wait_group 1;" ::: "memory"); }
__device__ __forceinline__ void cpw0() { asm volatile("cp.async.wait_group 0;" ::: "memory"); }
// fast split: hi = truncate to bf16 (bit mask), lo = exact residual rounded to bf16
__device__ __forceinline__ void split2(float a, float b, uint32_t& hi, uint32_t& lo) {
    uint32_t ua = __float_as_uint(a) & 0xFFFF0000u;
    uint32_t ub = __float_as_uint(b) & 0xFFFF0000u;
    hi = __byte_perm(ua, ub, 0x7632);
    float la = a - __uint_as_float(ua);
    float lb = b - __uint_as_float(ub);
    __nv_bfloat162 L = __floats2bfloat162_rn(la, lb);
    lo = *(uint32_t*)&L;
}

// ---------------- rope trig: fp64 arg + range reduction, fp32 trig ----------------
__device__ __forceinline__ float redang(double a) {
    double k = rint(a * 0.15915494309189535);         // 1/(2*pi)
    double r = fma(-k, 6.283185307179586, a);         // 2*pi hi
    r = fma(-k, 2.4492935982947064e-16, r);           // 2*pi lo
    return (float)r;
}

// ---------------- fused prologue: split-q | split-kv | prep_w | trig ----------------
__global__ void k_prep(const float* __restrict__ q, const float* __restrict__ kv,
                       const int* __restrict__ qc, const int* __restrict__ kc,
                       const float* __restrict__ Wq, const float* __restrict__ Wk,
                       const float* __restrict__ Wv, const float* __restrict__ Wo) {
    int bx = blockIdx.x, tid = threadIdx.x;
    if (bx < 16384) {
        const float* x = (bx < 8192) ? q : kv;
        bf16* oh = (bx < 8192) ? g_xqh : g_xkh;
        bf16* ol = (bx < 8192) ? g_xql : g_xkl;
        int i = (((bx & 8191) << 8) + tid) << 2;
        float4 v = *(const float4*)(x + i);
        uint32_t h0, l0, h1, l1;
        split2(v.x, v.y, h0, l0);
        split2(v.z, v.w, h1, l1);
        ((uint32_t*)oh)[i >> 1] = h0; ((uint32_t*)oh)[(i >> 1) + 1] = h1;
        ((uint32_t*)ol)[i >> 1] = l0; ((uint32_t*)ol)[(i >> 1) + 1] = l1;
    } else if (bx < 17408) {
        int idx = ((bx - 16384) << 8) + tid;
        int n = idx >> 10, i = idx & 1023;
        const float* bq = Wq + (size_t)i * 1024 + (n >> 6) * 256 + (n & 63);
        float s = bq[0] + bq[64] + bq[128] + bq[192];
        bf16 hh = __float2bfloat16_rn(s);
        g_wqt_h[(size_t)n * 1024 + i] = hh;
        g_wqt_l[(size_t)n * 1024 + i] = __float2bfloat16_rn(s - __bfloat162float(hh));
        float vk = Wk[(size_t)i * 256 + n];
        hh = __float2bfloat16_rn(vk);
        g_wkt_h[(size_t)n * 1024 + i] = hh;
        g_wkt_l[(size_t)n * 1024 + i] = __float2bfloat16_rn(vk - __bfloat162float(hh));
        float vv = Wv[(size_t)i * 256 + n];
        hh = __float2bfloat16_rn(vv);
        g_wvt_h[(size_t)n * 1024 + i] = hh;
        g_wvt_l[(size_t)n * 1024 + i] = __float2bfloat16_rn(vv - __bfloat162float(hh));
        int n2 = idx >> 8, k2 = idx & 255;
        float vo = Wo[(size_t)k2 * 1024 + n2];
        hh = __float2bfloat16_rn(vo);
        g_wot_h[(size_t)n2 * 256 + k2] = hh;
        g_wot_l[(size_t)n2 * 256 + k2] = __float2bfloat16_rn(vo - __bfloat162float(hh));
    } else {
        int idx = ((bx - 17408) << 8) + tid;
        int p = idx & 31, tok = idx >> 5;
        int axis = p >> 4, f = p & 15;
        double inv = c_invf[f];
        float aq = redang((double)qc[tok * 2 + axis] * inv);
        float ak = redang((double)kc[tok * 2 + axis] * inv);
        g_trq[idx] = make_float2(cosf(aq), sinf(aq));
        g_trk[idx] = make_float2(cosf(ak), sinf(ak));
    }
}

// ---------------- HMMA GEMM, cp.async 2-stage, BK=64, 512 threads ----------------
// 16 warps, warp grid 4x4, warp tile 32x32 (mt=2 x nt=4). 1 CTA/SM but 4 warps/SMSP.
// stage layout: AH 0 | AL 16K | BH 32K | BL 48K; stage stride 64K; 128KB total.
__device__ void dev_gemm(const bf16* __restrict__ Ah_, const bf16* __restrict__ Al_,
                         const bf16* __restrict__ Bh_, const bf16* __restrict__ Bl_,
                         float* __restrict__ C, int K, int mode, int m0, int n0,
                         const float2* __restrict__ trig, float scale,
                         bf16* __restrict__ oh_, bf16* __restrict__ ol_) {
    extern __shared__ __align__(128) uint8_t smg[];
    uint32_t S = smem_u32(smg);
    const int tid = threadIdx.x, l = tid & 31, w = tid >> 5;
    const int wm = (w & 3) << 5, wn = (w >> 2) << 5;
    const int nk = K >> 6;

    int sr[2], sc[2]; uint32_t so[2];
#pragma unroll
    for (int i = 0; i < 2; i++) {
        int slot = tid + (i << 9);
        sr[i] = slot >> 3; sc[i] = slot & 7;
        so[i] = sr[i] * 128 + ((sc[i] ^ (sr[i] & 7)) << 4);
    }
    auto issue = [&](int ck, int st) {
        uint32_t B = S + st * 65536;
        int kb = ck << 6;
#pragma unroll
        for (int i = 0; i < 2; i++) {
            size_t ga = (size_t)(m0 + sr[i]) * K + kb + sc[i] * 8;
            size_t gb = (size_t)(n0 + sr[i]) * K + kb + sc[i] * 8;
            cpa(B + so[i],         Ah_ + ga);
            cpa(B + 16384 + so[i], Al_ + ga);
            cpa(B + 32768 + so[i], Bh_ + gb);
            cpa(B + 49152 + so[i], Bl_ + gb);
        }
        cpc();
    };

    uint32_t aOff[2][4], bOff[2][4];
#pragma unroll
    for (int mt = 0; mt < 2; mt++) {
        int r = wm + mt * 16 + (l & 15);
#pragma unroll
        for (int ks = 0; ks < 4; ks++) {
            int cg = ks * 2 + (l >> 4);
            aOff[mt][ks] = r * 128 + ((cg ^ (r & 7)) << 4);
        }
    }
#pragma unroll
    for (int p = 0; p < 2; p++) {
        int r = wn + p * 16 + ((l >> 4) << 3) + (l & 7);
#pragma unroll
        for (int ks = 0; ks < 4; ks++) {
            int cg = ks * 2 + ((l >> 3) & 1);
            bOff[p][ks] = 32768 + r * 128 + ((cg ^ (r & 7)) << 4);
        }
    }

    float acc[2][4][4] = {};
    issue(0, 0);
    if (nk > 1) issue(1, 1);
    for (int t = 0; t < nk; t++) {
        if (t + 1 < nk) cpw1(); else cpw0();
        __syncthreads();
        uint32_t SB = S + (t & 1) * 65536;
#pragma unroll
        for (int ks = 0; ks < 4; ks++) {
            uint32_t Ahf[2][4], Alf[2][4], BHf[2][4], BLf[2][4];
#pragma unroll
            for (int mt = 0; mt < 2; mt++) {
                ldsm4(SB + aOff[mt][ks], Ahf[mt]);
                ldsm4(SB + aOff[mt][ks] + 16384, Alf[mt]);
            }
#pragma unroll
            for (int p = 0; p < 2; p++) {
                ldsm4(SB + bOff[p][ks], BHf[p]);
                ldsm4(SB + bOff[p][ks] + 16384, BLf[p]);
            }
#pragma unroll
            for (int p = 0; p < 2; p++)
#pragma unroll
            for (int q = 0; q < 2; q++)
#pragma unroll
            for (int mt = 0; mt < 2; mt++)
                mma16816(acc[mt][2 * p + q], Ahf[mt], BHf[p] + 2 * q);
#pragma unroll
            for (int p = 0; p < 2; p++)
#pragma unroll
            for (int q = 0; q < 2; q++)
#pragma unroll
            for (int mt = 0; mt < 2; mt++)
                mma16816(acc[mt][2 * p + q], Ahf[mt], BLf[p] + 2 * q);
#pragma unroll
            for (int p = 0; p < 2; p++)
#pragma unroll
            for (int q = 0; q < 2; q++)
#pragma unroll
            for (int mt = 0; mt < 2; mt++)
                mma16816(acc[mt][2 * p + q], Alf[mt], BHf[p] + 2 * q);
        }
        __syncthreads();
        if (t + 2 < nk) issue(t + 2, t & 1);
    }

    const int tq = l >> 2, tr = l & 3;
#pragma unroll
    for (int mt = 0; mt < 2; mt++)
#pragma unroll
    for (int nt = 0; nt < 4; nt++) {
        int row = m0 + wm + mt * 16 + tq;
        int col = n0 + wn + nt * 8 + 2 * tr;
        float* a4 = acc[mt][nt];
        if (mode == 0) {
            *(float2*)(C + (size_t)row * 1024 + col) = make_float2(a4[0], a4[1]);
            *(float2*)(C + (size_t)(row + 8) * 1024 + col) = make_float2(a4[2], a4[3]);
        } else {
            int hh = col >> 6, dd = col & 63;
#pragma unroll
            for (int half = 0; half < 2; half++) {
                int rr = row + (half << 3);
                size_t idx = (((size_t)(rr >> 11) * 4 + hh) * 2048 + (rr & 2047)) * 64 + dd;
                float x1 = a4[2 * half], x2 = a4[2 * half + 1];
                uint32_t hi, lo;
                if (mode == 1) {
                    float2 cs = trig[(size_t)rr * 32 + (dd >> 1)];
                    float y1 = (x1 * cs.x - x2 * cs.y) * scale;
                    float y2 = (x1 * cs.y + x2 * cs.x) * scale;
                    split2(y1, y2, hi, lo);
                } else {
                    split2(x1, x2, hi, lo);
                }
                *(uint32_t*)(oh_ + idx) = hi;
                *(uint32_t*)(ol_ + idx) = lo;
            }
        }
    }
}

__global__ __launch_bounds__(512, 1) void k_proj() {
    int n0 = blockIdx.x * 128, m0 = blockIdx.y * 128, z = blockIdx.z;
    if (z == 0)
        dev_gemm(g_xqh, g_xql, g_wqt_h, g_wqt_l, (float*)0, 1024, 1, m0, n0, g_trq, 0.125f, g_qh, g_ql);
    else if (z == 1)
        dev_gemm(g_xkh, g_xkl, g_wkt_h, g_wkt_l, (float*)0, 1024, 1, m0, n0, g_trk, 1.0f, g_kh, g_kl);
    else
        dev_gemm(g_xkh, g_xkl, g_wvt_h, g_wvt_l, (float*)0, 1024, 2, m0, n0, (const float2*)0, 1.0f, g_vh, g_vl);
}
__global__ __launch_bounds__(512, 1) void k_outproj(float* out) {
    dev_gemm(g_aoh, g_aol, g_wot_h, g_wot_l, out, 256, 0, blockIdx.y * 128, blockIdx.x * 128,
             (const float2*)0, 1.0f, (bf16*)0, (bf16*)0);
}

// ---------------- flash attention, cp.async 2-stage (unchanged from R10) --------
__global__ __launch_bounds__(256, 1) void k_attn() {
    extern __shared__ __align__(128) uint8_t smb[];
    uint32_t S = smem_u32(smb);
    const int tid = threadIdx.x, l = tid & 31, w = tid >> 5;
    const int qt = blockIdx.x, h = blockIdx.y, b = blockIdx.z;
    const int bh = b * 4 + h, q0 = qt * 128;

    int sr[4], sc[4]; uint32_t so[4];
#pragma unroll
    for (int i = 0; i < 4; i++) {
        int slot = tid + (i << 8);
        sr[i] = slot >> 3; sc[i] = slot & 7;
        so[i] = sr[i] * 128 + ((sc[i] ^ (sr[i] & 7)) << 4);
    }
    const bf16* bKH = g_kh + (size_t)bh * 2048 * 64;
    const bf16* bKL = g_kl + (size_t)bh * 2048 * 64;
    const bf16* bVH = g_vh + (size_t)bh * 2048 * 64;
    const bf16* bVL = g_vl + (size_t)bh * 2048 * 64;
    auto issueKV = [&](int it, int st) {
        uint32_t B = S + st * 65536;
        size_t t0 = (size_t)(it * 128) * 64;
#pragma unroll
        for (int i = 0; i < 4; i++) {
            size_t g = t0 + (size_t)sr[i] * 64 + sc[i] * 8;
            cpa(B + so[i],         bKH + g);
            cpa(B + 16384 + so[i], bKL + g);
            cpa(B + 32768 + so[i], bVH + g);
            cpa(B + 49152 + so[i], bVL + g);
        }
        cpc();
    };

    issueKV(0, 0);
    {   // Q staged into stage1 K regions
        const bf16* gQH = g_qh + ((size_t)bh * 2048 + q0) * 64;
        const bf16* gQL = g_ql + ((size_t)bh * 2048 + q0) * 64;
        uint32_t B = S + 65536;
#pragma unroll
        for (int i = 0; i < 4; i++) {
            size_t g = (size_t)sr[i] * 64 + sc[i] * 8;
            cpa(B + so[i],         gQH + g);
            cpa(B + 16384 + so[i], gQL + g);
        }
        cpc();
    }
    cpw0();
    __syncthreads();
    uint32_t Qh[4][4], Ql[4][4];
    {
        int r = w * 16 + (l & 15);
#pragma unroll
        for (int ks = 0; ks < 4; ks++) {
            int cg = ks * 2 + (l >> 4);
            uint32_t a = S + 65536 + r * 128 + ((cg ^ (r & 7)) << 4);
            ldsm4(a, Qh[ks]);
            ldsm4(a + 16384, Ql[ks]);
        }
    }
    __syncthreads();
    issueKV(1, 1);

    float O[8][4] = {};
    float lr0 = 0.f, lr1 = 0.f;
    const int bRowK = ((l >> 4) << 3) + (l & 7);
    const int kc = (l >> 3) & 1;
    const int rV = l & 15, cgV = l >> 4;

    for (int it = 0; it < 16; it++) {
        if (it < 15) cpw1(); else cpw0();
        __syncthreads();
        uint32_t SB = S + (it & 1) * 65536;

        // S = Q K^T — K n-tiles processed in pairs, pass-major
        float sacc[16][4] = {};
#pragma unroll
        for (int ks = 0; ks < 4; ks++) {
#pragma unroll
            for (int pp = 0; pp < 4; pp++) {
                int p0 = 2 * pp, p1 = 2 * pp + 1;
                int br0 = p0 * 16 + bRowK, br1 = p1 * 16 + bRowK;
                uint32_t ab0 = SB + br0 * 128 + (((ks * 2 + kc) ^ (br0 & 7)) << 4);
                uint32_t ab1 = SB + br1 * 128 + (((ks * 2 + kc) ^ (br1 & 7)) << 4);
                uint32_t BH0[4], BL0[4], BH1[4], BL1[4];
                ldsm4(ab0, BH0); ldsm4(ab0 + 16384, BL0);
                ldsm4(ab1, BH1); ldsm4(ab1 + 16384, BL1);
#pragma unroll
                for (int q = 0; q < 2; q++) mma16816(sacc[2 * p0 + q], Qh[ks], BH0 + 2 * q);
#pragma unroll
                for (int q = 0; q < 2; q++) mma16816(sacc[2 * p1 + q], Qh[ks], BH1 + 2 * q);
#pragma unroll
                for (int q = 0; q < 2; q++) mma16816(sacc[2 * p0 + q], Qh[ks], BL0 + 2 * q);
#pragma unroll
                for (int q = 0; q < 2; q++) mma16816(sacc[2 * p1 + q], Qh[ks], BL1 + 2 * q);
#pragma unroll
                for (int q = 0; q < 2; q++) mma16816(sacc[2 * p0 + q], Ql[ks], BH0 + 2 * q);
#pragma unroll
                for (int q = 0; q < 2; q++) mma16816(sacc[2 * p1 + q], Ql[ks], BH1 + 2 * q);
            }
        }

        // exp (bounded scores) + PV — V d-tiles in pairs, pass-major
#pragma unroll
        for (int j = 0; j < 8; j++) {
            uint32_t Ph[4], Pl[4];
#pragma unroll
            for (int q = 0; q < 2; q++) {
                float* sa = sacc[2 * j + q];
                float p0 = __expf(sa[0]), p1 = __expf(sa[1]);
                float p2 = __expf(sa[2]), p3 = __expf(sa[3]);
                lr0 += p0 + p1; lr1 += p2 + p3;
                split2(p0, p1, Ph[2 * q], Pl[2 * q]);
                split2(p2, p3, Ph[2 * q + 1], Pl[2 * q + 1]);
            }
            int r2 = j * 16 + rV;
#pragma unroll
            for (int pp = 0; pp < 2; pp++) {
                int p0 = 2 * pp, p1 = 2 * pp + 1;
                uint32_t av0 = SB + 32768 + r2 * 128 + (((p0 * 2 + cgV) ^ (r2 & 7)) << 4);
                uint32_t av1 = SB + 32768 + r2 * 128 + (((p1 * 2 + cgV) ^ (r2 & 7)) << 4);
                uint32_t VH0[4], VL0[4], VH1[4], VL1[4];
                ldsm4t(av0, VH0); ldsm4t(av0 + 16384, VL0);
                ldsm4t(av1, VH1); ldsm4t(av1 + 16384, VL1);
#pragma unroll
                for (int q = 0; q < 2; q++) mma16816(O[2 * p0 + q], Ph, VH0 + 2 * q);
#pragma unroll
                for (int q = 0; q < 2; q++) mma16816(O[2 * p1 + q], Ph, VH1 + 2 * q);
#pragma unroll
                for (int q = 0; q < 2; q++) mma16816(O[2 * p0 + q], Ph, VL0 + 2 * q);
#pragma unroll
                for (int q = 0; q < 2; q++) mma16816(O[2 * p1 + q], Ph, VL1 + 2 * q);
#pragma unroll
                for (int q = 0; q < 2; q++) mma16816(O[2 * p0 + q], Pl, VH0 + 2 * q);
#pragma unroll
                for (int q = 0; q < 2; q++) mma16816(O[2 * p1 + q], Pl, VH1 + 2 * q);
            }
        }
        __syncthreads();
        if (it + 2 < 16) issueKV(it + 2, it & 1);
    }

    lr0 += __shfl_xor_sync(0xffffffffu, lr0, 1);
    lr0 += __shfl_xor_sync(0xffffffffu, lr0, 2);
    lr1 += __shfl_xor_sync(0xffffffffu, lr1, 1);
    lr1 += __shfl_xor_sync(0xffffffffu, lr1, 2);
    float i0 = 1.f / lr0, i1 = 1.f / lr1;

    const int tq = l >> 2, tr = l & 3;
    size_t tok0 = (size_t)b * 2048 + q0 + w * 16 + tq;
#pragma unroll
    for (int dt = 0; dt < 8; dt++) {
        int c = h * 64 + dt * 8 + 2 * tr;
        uint32_t hi, lo;
        split2(O[dt][0] * i0, O[dt][1] * i0, hi, lo);
        *(uint32_t*)(g_aoh + tok0 * 256 + c) = hi;
        *(uint32_t*)(g_aol + tok0 * 256 + c) = lo;
        split2(O[dt][2] * i1, O[dt][3] * i1, hi, lo);
        *(uint32_t*)(g_aoh + (tok0 + 8) * 256 + c) = hi;
        *(uint32_t*)(g_aol + (tok0 + 8) * 256 + c) = lo;
    }
}

// ---------------- launch ----------------
#define PIPE_SMEM 131072

extern "C" void kernel_launch(void* const* d_in, const int* in_sizes, int n_in,
                              void* d_out, int out_size) {
    const float* q         = (const float*)d_in[0];
    const int*   q_coords  = (const int*)  d_in[1];
    const float* kv        = (const float*)d_in[2];
    const int*   kv_coords = (const int*)  d_in[3];
    const float* Wq        = (const float*)d_in[4];
    const float* Wk        = (const float*)d_in[5];
    const float* Wv        = (const float*)d_in[6];
    const float* Wo        = (const float*)d_in[7];
    float* out = (float*)d_out;

    cudaFuncSetAttribute(k_proj, cudaFuncAttributeMaxDynamicSharedMemorySize, PIPE_SMEM);
    cudaFuncSetAttribute(k_outproj, cudaFuncAttributeMaxDynamicSharedMemorySize, PIPE_SMEM);
    cudaFuncSetAttribute(k_attn, cudaFuncAttributeMaxDynamicSharedMemorySize, PIPE_SMEM);

    k_prep<<<18432, 256>>>(q, kv, q_coords, kv_coords, Wq, Wk, Wv, Wo);
    k_proj<<<dim3(2, 64, 3), 512, PIPE_SMEM>>>();
    k_attn<<<dim3(16, 4, 4), 256, PIPE_SMEM>>>();
    k_outproj<<<dim3(8, 64), 512, PIPE_SMEM>>>(out);
}

// round 15
// speedup vs baseline: 1.0265x; 1.0265x over previous
#include <cuda_runtime.h>
#include <cuda_bf16.h>
#include <cstdint>
#include <math.h>

#define SEQ 2048
#define IND 1024
#define HD 256
#define NTOK 8192
typedef __nv_bfloat16 bf16;

// ---------------- scratch (no allocs allowed) ----------------
__device__ __align__(16) bf16 g_xqh[NTOK*IND], g_xql[NTOK*IND];
__device__ __align__(16) bf16 g_xkh[NTOK*IND], g_xkl[NTOK*IND];
__device__ __align__(16) bf16 g_wqt_h[HD*IND], g_wqt_l[HD*IND];   // [256][1024] K-major
__device__ __align__(16) bf16 g_wkt_h[HD*IND], g_wkt_l[HD*IND];
__device__ __align__(16) bf16 g_wvt_h[HD*IND], g_wvt_l[HD*IND];
__device__ __align__(16) bf16 g_wot_h[IND*HD], g_wot_l[IND*HD];   // [1024][256] K-major
__device__ __align__(16) float2 g_trq[NTOK*32], g_trk[NTOK*32];   // rope cos/sin tables
__device__ __align__(16) bf16 g_qh[NTOK*HD], g_ql[NTOK*HD];       // roped+scaled [bh][s][64]
__device__ __align__(16) bf16 g_kh[NTOK*HD], g_kl[NTOK*HD];
__device__ __align__(16) bf16 g_vh[NTOK*HD], g_vl[NTOK*HD];       // [bh][s][64]
__device__ __align__(16) bf16 g_aoh[NTOK*HD], g_aol[NTOK*HD];     // [tok][256]

__constant__ double c_invf[16] = {
    1.0, 0.5623413251903491, 0.31622776601683794, 0.17782794100389228,
    0.1, 0.05623413251903491, 0.031622776601683791, 0.017782794100389228,
    0.01, 0.005623413251903491, 0.0031622776601683794, 0.0017782794100389228,
    0.001, 0.0005623413251903491, 0.00031622776601683794, 0.00017782794100389228};

// ---------------- helpers ----------------
__device__ __forceinline__ uint32_t smem_u32(const void* p) {
    uint32_t a;
    asm("{ .reg .u64 t; cvta.to.shared.u64 t, %1; cvt.u32.u64 %0, t; }" : "=r"(a) : "l"(p));
    return a;
}
__device__ __forceinline__ void ldsm4(uint32_t a, uint32_t* r) {
    asm volatile("ldmatrix.sync.aligned.m8n8.x4.shared.b16 {%0,%1,%2,%3}, [%4];"
        : "=r"(r[0]), "=r"(r[1]), "=r"(r[2]), "=r"(r[3]) : "r"(a));
}
__device__ __forceinline__ void ldsm4t(uint32_t a, uint32_t* r) {
    asm volatile("ldmatrix.sync.aligned.m8n8.x4.trans.shared.b16 {%0,%1,%2,%3}, [%4];"
        : "=r"(r[0]), "=r"(r[1]), "=r"(r[2]), "=r"(r[3]) : "r"(a));
}
__device__ __forceinline__ void mma16816(float* c, const uint32_t* a, const uint32_t* b) {
    asm volatile("mma.sync.aligned.m16n8k16.row.col.f32.bf16.bf16.f32 "
        "{%0,%1,%2,%3}, {%4,%5,%6,%7}, {%8,%9}, {%0,%1,%2,%3};"
        : "+f"(c[0]), "+f"(c[1]), "+f"(c[2]), "+f"(c[3])
        : "r"(a[0]), "r"(a[1]), "r"(a[2]), "r"(a[3]), "r"(b[0]), "r"(b[1]));
}
__device__ __forceinline__ void cpa(uint32_t s, const void* g) {
    asm volatile("cp.async.cg.shared.global [%0], [%1], 16;" :: "r"(s), "l"(g));
}
__device__ __forceinline__ void cpc()  { asm volatile("cp.async.commit_group;" ::: "memory"); }
__device__ __forceinline__ void cpw1() { asm volatile("cp.async.wait_group 1;" ::: "memory"); }
__device__ __forceinline__ void cpw0() { asm volatile("cp.async.wait_group 0;" ::: "memory"); }
// fast split: hi = truncate to bf16 (bit mask), lo = exact residual rounded to bf16
__device__ __forceinline__ void split2(float a, float b, uint32_t& hi, uint32_t& lo) {
    uint32_t ua = __float_as_uint(a) & 0xFFFF0000u;
    uint32_t ub = __float_as_uint(b) & 0xFFFF0000u;
    hi = __byte_perm(ua, ub, 0x7632);
    float la = a - __uint_as_float(ua);
    float lb = b - __uint_as_float(ub);
    __nv_bfloat162 L = __floats2bfloat162_rn(la, lb);
    lo = *(uint32_t*)&L;
}

// ---------------- rope trig: fp64 arg + range reduction, fp32 trig ----------------
__device__ __forceinline__ float redang(double a) {
    double k = rint(a * 0.15915494309189535);         // 1/(2*pi)
    double r = fma(-k, 6.283185307179586, a);         // 2*pi hi
    r = fma(-k, 2.4492935982947064e-16, r);           // 2*pi lo
    return (float)r;
}

// ---------------- fused prologue: split-q | split-kv | prep_w | trig ----------------
__global__ void k_prep(const float* __restrict__ q, const float* __restrict__ kv,
                       const int* __restrict__ qc, const int* __restrict__ kc,
                       const float* __restrict__ Wq, const float* __restrict__ Wk,
                       const float* __restrict__ Wv, const float* __restrict__ Wo) {
    int bx = blockIdx.x, tid = threadIdx.x;
    if (bx < 16384) {
        const float* x = (bx < 8192) ? q : kv;
        bf16* oh = (bx < 8192) ? g_xqh : g_xkh;
        bf16* ol = (bx < 8192) ? g_xql : g_xkl;
        int i = (((bx & 8191) << 8) + tid) << 2;
        float4 v = *(const float4*)(x + i);
        uint32_t h0, l0, h1, l1;
        split2(v.x, v.y, h0, l0);
        split2(v.z, v.w, h1, l1);
        ((uint32_t*)oh)[i >> 1] = h0; ((uint32_t*)oh)[(i >> 1) + 1] = h1;
        ((uint32_t*)ol)[i >> 1] = l0; ((uint32_t*)ol)[(i >> 1) + 1] = l1;
    } else if (bx < 17408) {
        int idx = ((bx - 16384) << 8) + tid;
        int n = idx >> 10, i = idx & 1023;
        const float* bq = Wq + (size_t)i * 1024 + (n >> 6) * 256 + (n & 63);
        float s = bq[0] + bq[64] + bq[128] + bq[192];
        bf16 hh = __float2bfloat16_rn(s);
        g_wqt_h[(size_t)n * 1024 + i] = hh;
        g_wqt_l[(size_t)n * 1024 + i] = __float2bfloat16_rn(s - __bfloat162float(hh));
        float vk = Wk[(size_t)i * 256 + n];
        hh = __float2bfloat16_rn(vk);
        g_wkt_h[(size_t)n * 1024 + i] = hh;
        g_wkt_l[(size_t)n * 1024 + i] = __float2bfloat16_rn(vk - __bfloat162float(hh));
        float vv = Wv[(size_t)i * 256 + n];
        hh = __float2bfloat16_rn(vv);
        g_wvt_h[(size_t)n * 1024 + i] = hh;
        g_wvt_l[(size_t)n * 1024 + i] = __float2bfloat16_rn(vv - __bfloat162float(hh));
        int n2 = idx >> 8, k2 = idx & 255;
        float vo = Wo[(size_t)k2 * 1024 + n2];
        hh = __float2bfloat16_rn(vo);
        g_wot_h[(size_t)n2 * 256 + k2] = hh;
        g_wot_l[(size_t)n2 * 256 + k2] = __float2bfloat16_rn(vo - __bfloat162float(hh));
    } else {
        int idx = ((bx - 17408) << 8) + tid;
        int p = idx & 31, tok = idx >> 5;
        int axis = p >> 4, f = p & 15;
        double inv = c_invf[f];
        float aq = redang((double)qc[tok * 2 + axis] * inv);
        float ak = redang((double)kc[tok * 2 + axis] * inv);
        g_trq[idx] = make_float2(cosf(aq), sinf(aq));
        g_trk[idx] = make_float2(cosf(ak), sinf(ak));
    }
}

// ---------------- HMMA GEMM, cp.async 2-stage, BK=32, 64KB smem -> 2 CTAs/SM ----
// 8 warps, warp grid 2x4, warp tile 64x32. Tile rows are 64B (32 bf16).
// swizzle: 16B-group c ^ ((r>>1)&3) — conflict-free for ldsm + cp.async stores.
// stage: AH 0 | AL 8K | BH 16K | BL 24K; stride 32K; 64KB total.
__device__ void dev_gemm(const bf16* __restrict__ Ah_, const bf16* __restrict__ Al_,
                         const bf16* __restrict__ Bh_, const bf16* __restrict__ Bl_,
                         float* __restrict__ C, int K, int mode, int m0, int n0,
                         const float2* __restrict__ trig, float scale,
                         bf16* __restrict__ oh_, bf16* __restrict__ ol_) {
    extern __shared__ __align__(128) uint8_t smg[];
    uint32_t S = smem_u32(smg);
    const int tid = threadIdx.x, l = tid & 31, w = tid >> 5;
    const int wm = (w & 1) << 6, wn = (w >> 1) << 5;
    const int nk = K >> 5;

    // staging: A and B each 128 rows x 4 sixteen-byte groups = 512 slots; 2/thread
    int sr[2], sc[2]; uint32_t so[2];
#pragma unroll
    for (int i = 0; i < 2; i++) {
        int slot = tid + (i << 8);
        sr[i] = slot >> 2; sc[i] = slot & 3;
        so[i] = sr[i] * 64 + ((sc[i] ^ ((sr[i] >> 1) & 3)) << 4);
    }
    auto issue = [&](int ck, int st) {
        uint32_t B = S + st * 32768;
        int kb = ck << 5;
#pragma unroll
        for (int i = 0; i < 2; i++) {
            size_t ga = (size_t)(m0 + sr[i]) * K + kb + sc[i] * 8;
            size_t gb = (size_t)(n0 + sr[i]) * K + kb + sc[i] * 8;
            cpa(B + so[i],         Ah_ + ga);
            cpa(B + 8192 + so[i],  Al_ + ga);
            cpa(B + 16384 + so[i], Bh_ + gb);
            cpa(B + 24576 + so[i], Bl_ + gb);
        }
        cpc();
    };

    uint32_t aOff[4][2], bOff[2][2];
#pragma unroll
    for (int mt = 0; mt < 4; mt++) {
        int r = wm + mt * 16 + (l & 15);
#pragma unroll
        for (int ks = 0; ks < 2; ks++) {
            int cg = ks * 2 + (l >> 4);
            aOff[mt][ks] = r * 64 + ((cg ^ ((r >> 1) & 3)) << 4);
        }
    }
#pragma unroll
    for (int p = 0; p < 2; p++) {
        int r = wn + p * 16 + ((l >> 4) << 3) + (l & 7);
#pragma unroll
        for (int ks = 0; ks < 2; ks++) {
            int cg = ks * 2 + ((l >> 3) & 1);
            bOff[p][ks] = 16384 + r * 64 + ((cg ^ ((r >> 1) & 3)) << 4);
        }
    }

    float acc[4][4][4] = {};
    issue(0, 0);
    if (nk > 1) issue(1, 1);
    for (int t = 0; t < nk; t++) {
        if (t + 1 < nk) cpw1(); else cpw0();
        __syncthreads();
        uint32_t SB = S + (t & 1) * 32768;
#pragma unroll
        for (int ks = 0; ks < 2; ks++) {
            uint32_t Ahf[4][4], Alf[4][4], BHf[2][4], BLf[2][4];
#pragma unroll
            for (int mt = 0; mt < 4; mt++) {
                ldsm4(SB + aOff[mt][ks], Ahf[mt]);
                ldsm4(SB + aOff[mt][ks] + 8192, Alf[mt]);
            }
#pragma unroll
            for (int p = 0; p < 2; p++) {
                ldsm4(SB + bOff[p][ks], BHf[p]);
                ldsm4(SB + bOff[p][ks] + 8192, BLf[p]);
            }
#pragma unroll
            for (int p = 0; p < 2; p++)
#pragma unroll
            for (int q = 0; q < 2; q++)
#pragma unroll
            for (int mt = 0; mt < 4; mt++)
                mma16816(acc[mt][2 * p + q], Ahf[mt], BHf[p] + 2 * q);
#pragma unroll
            for (int p = 0; p < 2; p++)
#pragma unroll
            for (int q = 0; q < 2; q++)
#pragma unroll
            for (int mt = 0; mt < 4; mt++)
                mma16816(acc[mt][2 * p + q], Ahf[mt], BLf[p] + 2 * q);
#pragma unroll
            for (int p = 0; p < 2; p++)
#pragma unroll
            for (int q = 0; q < 2; q++)
#pragma unroll
            for (int mt = 0; mt < 4; mt++)
                mma16816(acc[mt][2 * p + q], Alf[mt], BHf[p] + 2 * q);
        }
        __syncthreads();
        if (t + 2 < nk) issue(t + 2, t & 1);
    }

    const int tq = l >> 2, tr = l & 3;
#pragma unroll
    for (int mt = 0; mt < 4; mt++)
#pragma unroll
    for (int nt = 0; nt < 4; nt++) {
        int row = m0 + wm + mt * 16 + tq;
        int col = n0 + wn + nt * 8 + 2 * tr;
        float* a4 = acc[mt][nt];
        if (mode == 0) {
            *(float2*)(C + (size_t)row * 1024 + col) = make_float2(a4[0], a4[1]);
            *(float2*)(C + (size_t)(row + 8) * 1024 + col) = make_float2(a4[2], a4[3]);
        } else {
            int hh = col >> 6, dd = col & 63;
#pragma unroll
            for (int half = 0; half < 2; half++) {
                int rr = row + (half << 3);
                size_t idx = (((size_t)(rr >> 11) * 4 + hh) * 2048 + (rr & 2047)) * 64 + dd;
                float x1 = a4[2 * half], x2 = a4[2 * half + 1];
                uint32_t hi, lo;
                if (mode == 1) {
                    float2 cs = trig[(size_t)rr * 32 + (dd >> 1)];
                    float y1 = (x1 * cs.x - x2 * cs.y) * scale;
                    float y2 = (x1 * cs.y + x2 * cs.x) * scale;
                    split2(y1, y2, hi, lo);
                } else {
                    split2(x1, x2, hi, lo);
                }
                *(uint32_t*)(oh_ + idx) = hi;
                *(uint32_t*)(ol_ + idx) = lo;
            }
        }
    }
}

__global__ __launch_bounds__(256, 2) void k_proj() {
    int n0 = blockIdx.x * 128, m0 = blockIdx.y * 128, z = blockIdx.z;
    if (z == 0)
        dev_gemm(g_xqh, g_xql, g_wqt_h, g_wqt_l, (float*)0, 1024, 1, m0, n0, g_trq, 0.125f, g_qh, g_ql);
    else if (z == 1)
        dev_gemm(g_xkh, g_xkl, g_wkt_h, g_wkt_l, (float*)0, 1024, 1, m0, n0, g_trk, 1.0f, g_kh, g_kl);
    else
        dev_gemm(g_xkh, g_xkl, g_wvt_h, g_wvt_l, (float*)0, 1024, 2, m0, n0, (const float2*)0, 1.0f, g_vh, g_vl);
}
__global__ __launch_bounds__(256, 2) void k_outproj(float* out) {
    dev_gemm(g_aoh, g_aol, g_wot_h, g_wot_l, out, 256, 0, blockIdx.y * 128, blockIdx.x * 128,
             (const float2*)0, 1.0f, (bf16*)0, (bf16*)0);
}

// ---------------- flash attention, cp.async 2-stage (unchanged) ----------------
__global__ __launch_bounds__(256, 1) void k_attn() {
    extern __shared__ __align__(128) uint8_t smb[];
    uint32_t S = smem_u32(smb);
    const int tid = threadIdx.x, l = tid & 31, w = tid >> 5;
    const int qt = blockIdx.x, h = blockIdx.y, b = blockIdx.z;
    const int bh = b * 4 + h, q0 = qt * 128;

    int sr[4], sc[4]; uint32_t so[4];
#pragma unroll
    for (int i = 0; i < 4; i++) {
        int slot = tid + (i << 8);
        sr[i] = slot >> 3; sc[i] = slot & 7;
        so[i] = sr[i] * 128 + ((sc[i] ^ (sr[i] & 7)) << 4);
    }
    const bf16* bKH = g_kh + (size_t)bh * 2048 * 64;
    const bf16* bKL = g_kl + (size_t)bh * 2048 * 64;
    const bf16* bVH = g_vh + (size_t)bh * 2048 * 64;
    const bf16* bVL = g_vl + (size_t)bh * 2048 * 64;
    auto issueKV = [&](int it, int st) {
        uint32_t B = S + st * 65536;
        size_t t0 = (size_t)(it * 128) * 64;
#pragma unroll
        for (int i = 0; i < 4; i++) {
            size_t g = t0 + (size_t)sr[i] * 64 + sc[i] * 8;
            cpa(B + so[i],         bKH + g);
            cpa(B + 16384 + so[i], bKL + g);
            cpa(B + 32768 + so[i], bVH + g);
            cpa(B + 49152 + so[i], bVL + g);
        }
        cpc();
    };

    issueKV(0, 0);
    {   // Q staged into stage1 K regions
        const bf16* gQH = g_qh + ((size_t)bh * 2048 + q0) * 64;
        const bf16* gQL = g_ql + ((size_t)bh * 2048 + q0) * 64;
        uint32_t B = S + 65536;
#pragma unroll
        for (int i = 0; i < 4; i++) {
            size_t g = (size_t)sr[i] * 64 + sc[i] * 8;
            cpa(B + so[i],         gQH + g);
            cpa(B + 16384 + so[i], gQL + g);
        }
        cpc();
    }
    cpw0();
    __syncthreads();
    uint32_t Qh[4][4], Ql[4][4];
    {
        int r = w * 16 + (l & 15);
#pragma unroll
        for (int ks = 0; ks < 4; ks++) {
            int cg = ks * 2 + (l >> 4);
            uint32_t a = S + 65536 + r * 128 + ((cg ^ (r & 7)) << 4);
            ldsm4(a, Qh[ks]);
            ldsm4(a + 16384, Ql[ks]);
        }
    }
    __syncthreads();
    issueKV(1, 1);

    float O[8][4] = {};
    float lr0 = 0.f, lr1 = 0.f;
    const int bRowK = ((l >> 4) << 3) + (l & 7);
    const int kc = (l >> 3) & 1;
    const int rV = l & 15, cgV = l >> 4;

    for (int it = 0; it < 16; it++) {
        if (it < 15) cpw1(); else cpw0();
        __syncthreads();
        uint32_t SB = S + (it & 1) * 65536;

        // S = Q K^T — K n-tiles processed in pairs, pass-major
        float sacc[16][4] = {};
#pragma unroll
        for (int ks = 0; ks < 4; ks++) {
#pragma unroll
            for (int pp = 0; pp < 4; pp++) {
                int p0 = 2 * pp, p1 = 2 * pp + 1;
                int br0 = p0 * 16 + bRowK, br1 = p1 * 16 + bRowK;
                uint32_t ab0 = SB + br0 * 128 + (((ks * 2 + kc) ^ (br0 & 7)) << 4);
                uint32_t ab1 = SB + br1 * 128 + (((ks * 2 + kc) ^ (br1 & 7)) << 4);
                uint32_t BH0[4], BL0[4], BH1[4], BL1[4];
                ldsm4(ab0, BH0); ldsm4(ab0 + 16384, BL0);
                ldsm4(ab1, BH1); ldsm4(ab1 + 16384, BL1);
#pragma unroll
                for (int q = 0; q < 2; q++) mma16816(sacc[2 * p0 + q], Qh[ks], BH0 + 2 * q);
#pragma unroll
                for (int q = 0; q < 2; q++) mma16816(sacc[2 * p1 + q], Qh[ks], BH1 + 2 * q);
#pragma unroll
                for (int q = 0; q < 2; q++) mma16816(sacc[2 * p0 + q], Qh[ks], BL0 + 2 * q);
#pragma unroll
                for (int q = 0; q < 2; q++) mma16816(sacc[2 * p1 + q], Qh[ks], BL1 + 2 * q);
#pragma unroll
                for (int q = 0; q < 2; q++) mma16816(sacc[2 * p0 + q], Ql[ks], BH0 + 2 * q);
#pragma unroll
                for (int q = 0; q < 2; q++) mma16816(sacc[2 * p1 + q], Ql[ks], BH1 + 2 * q);
            }
        }

        // exp (bounded scores) + PV — V d-tiles in pairs, pass-major
#pragma unroll
        for (int j = 0; j < 8; j++) {
            uint32_t Ph[4], Pl[4];
#pragma unroll
            for (int q = 0; q < 2; q++) {
                float* sa = sacc[2 * j + q];
                float p0 = __expf(sa[0]), p1 = __expf(sa[1]);
                float p2 = __expf(sa[2]), p3 = __expf(sa[3]);
                lr0 += p0 + p1; lr1 += p2 + p3;
                split2(p0, p1, Ph[2 * q], Pl[2 * q]);
                split2(p2, p3, Ph[2 * q + 1], Pl[2 * q + 1]);
            }
            int r2 = j * 16 + rV;
#pragma unroll
            for (int pp = 0; pp < 2; pp++) {
                int p0 = 2 * pp, p1 = 2 * pp + 1;
                uint32_t av0 = SB + 32768 + r2 * 128 + (((p0 * 2 + cgV) ^ (r2 & 7)) << 4);
                uint32_t av1 = SB + 32768 + r2 * 128 + (((p1 * 2 + cgV) ^ (r2 & 7)) << 4);
                uint32_t VH0[4], VL0[4], VH1[4], VL1[4];
                ldsm4t(av0, VH0); ldsm4t(av0 + 16384, VL0);
                ldsm4t(av1, VH1); ldsm4t(av1 + 16384, VL1);
#pragma unroll
                for (int q = 0; q < 2; q++) mma16816(O[2 * p0 + q], Ph, VH0 + 2 * q);
#pragma unroll
                for (int q = 0; q < 2; q++) mma16816(O[2 * p1 + q], Ph, VH1 + 2 * q);
#pragma unroll
                for (int q = 0; q < 2; q++) mma16816(O[2 * p0 + q], Ph, VL0 + 2 * q);
#pragma unroll
                for (int q = 0; q < 2; q++) mma16816(O[2 * p1 + q], Ph, VL1 + 2 * q);
#pragma unroll
                for (int q = 0; q < 2; q++) mma16816(O[2 * p0 + q], Pl, VH0 + 2 * q);
#pragma unroll
                for (int q = 0; q < 2; q++) mma16816(O[2 * p1 + q], Pl, VH1 + 2 * q);
            }
        }
        __syncthreads();
        if (it + 2 < 16) issueKV(it + 2, it & 1);
    }

    lr0 += __shfl_xor_sync(0xffffffffu, lr0, 1);
    lr0 += __shfl_xor_sync(0xffffffffu, lr0, 2);
    lr1 += __shfl_xor_sync(0xffffffffu, lr1, 1);
    lr1 += __shfl_xor_sync(0xffffffffu, lr1, 2);
    float i0 = 1.f / lr0, i1 = 1.f / lr1;

    const int tq = l >> 2, tr = l & 3;
    size_t tok0 = (size_t)b * 2048 + q0 + w * 16 + tq;
#pragma unroll
    for (int dt = 0; dt < 8; dt++) {
        int c = h * 64 + dt * 8 + 2 * tr;
        uint32_t hi, lo;
        split2(O[dt][0] * i0, O[dt][1] * i0, hi, lo);
        *(uint32_t*)(g_aoh + tok0 * 256 + c) = hi;
        *(uint32_t*)(g_aol + tok0 * 256 + c) = lo;
        split2(O[dt][2] * i1, O[dt][3] * i1, hi, lo);
        *(uint32_t*)(g_aoh + (tok0 + 8) * 256 + c) = hi;
        *(uint32_t*)(g_aol + (tok0 + 8) * 256 + c) = lo;
    }
}

// ---------------- launch ----------------
#define GEMM_SMEM 65536
#define ATTN_SMEM 131072

extern "C" void kernel_launch(void* const* d_in, const int* in_sizes, int n_in,
                              void* d_out, int out_size) {
    const float* q         = (const float*)d_in[0];
    const int*   q_coords  = (const int*)  d_in[1];
    const float* kv        = (const float*)d_in[2];
    const int*   kv_coords = (const int*)  d_in[3];
    const float* Wq        = (const float*)d_in[4];
    const float* Wk        = (const float*)d_in[5];
    const float* Wv        = (const float*)d_in[6];
    const float* Wo        = (const float*)d_in[7];
    float* out = (float*)d_out;

    cudaFuncSetAttribute(k_proj, cudaFuncAttributeMaxDynamicSharedMemorySize, GEMM_SMEM);
    cudaFuncSetAttribute(k_outproj, cudaFuncAttributeMaxDynamicSharedMemorySize, GEMM_SMEM);
    cudaFuncSetAttribute(k_attn, cudaFuncAttributeMaxDynamicSharedMemorySize, ATTN_SMEM);

    k_prep<<<18432, 256>>>(q, kv, q_coords, kv_coords, Wq, Wk, Wv, Wo);
    k_proj<<<dim3(2, 64, 3), 256, GEMM_SMEM>>>();
    k_attn<<<dim3(16, 4, 4), 256, ATTN_SMEM>>>();
    k_outproj<<<dim3(8, 64), 256, GEMM_SMEM>>>(out);
}